// round 10
// baseline (speedup 1.0000x reference)
#include <cuda_runtime.h>
#include <math.h>

// DAGMixer R10: R9 structure, 2 rows per CTA (512 threads) to amortize the
// per-row reduce/barrier dead window.
//   logits[row] = dot(orig[row], W[0:H]) + dot(dag[row], W[H:2H]) + b
//   gate = sigmoid(logits); mixed[row] = orig + gate*(dag - orig)
// rows = B*T = 16384 (even), H = 2048 (fp32).
//
// Grid = rows/2 CTAs, 512 threads, 4 CTAs/SM (full 2048 thr/SM). Thread t
// covers float4 index t of BOTH rows (rowA = 2*bid, rowB = 2*bid+1). Live
// register set across the barriers is 16 data floats/thread (same as R9);
// W loads are consumed-immediately temporaries, loaded ONCE per CTA for
// both rows. Gate A finalized by tid 0, gate B by tid 32 (parallel warps).
// The reduce/BAR/sigmoid window is paid once per 32KB of traffic instead
// of once per 16KB.

#define THREADS 512
#define H_DIM   2048
#define F4_ROW  (H_DIM / 4)   // 512 float4 per row = 1 per thread
#define NWARP   (THREADS / 32)

__global__ __launch_bounds__(THREADS, 4)
void dagmixer_kernel(const float* __restrict__ orig,
                     const float* __restrict__ dag,
                     const float* __restrict__ w,     // [2H]: W_o then W_d
                     const float* __restrict__ bgate, // [1]
                     float* __restrict__ mixed,       // [rows*H]
                     float* __restrict__ gate_out)    // [rows]
{
    const int rowA = blockIdx.x * 2;
    const int tid  = threadIdx.x;

    const float4* __restrict__ oA = (const float4*)(orig + (size_t)rowA * H_DIM);
    const float4* __restrict__ dA = (const float4*)(dag  + (size_t)rowA * H_DIM);
    const float4* __restrict__ oB = oA + F4_ROW;
    const float4* __restrict__ dB = dA + F4_ROW;

    // Row data: 4 float4 live across the barrier (16 floats, same as R9).
    const float4 ovA = oA[tid];
    const float4 dvA = dA[tid];
    const float4 ovB = oB[tid];
    const float4 dvB = dB[tid];

    // W loaded once per CTA, consumed immediately (temporaries).
    const float4 a = ((const float4*)w)[tid];
    const float4 c = ((const float4*)(w + H_DIM))[tid];

    float pA = ovA.x * a.x + ovA.y * a.y + ovA.z * a.z + ovA.w * a.w
             + dvA.x * c.x + dvA.y * c.y + dvA.z * c.z + dvA.w * c.w;
    float pB = ovB.x * a.x + ovB.y * a.y + ovB.z * a.z + ovB.w * a.w
             + dvB.x * c.x + dvB.y * c.y + dvB.z * c.z + dvB.w * c.w;

    // Warp reduce both partials (interleaved shfl chains).
    #pragma unroll
    for (int off = 16; off > 0; off >>= 1) {
        pA += __shfl_xor_sync(0xffffffff, pA, off);
        pB += __shfl_xor_sync(0xffffffff, pB, off);
    }

    __shared__ float wsA[NWARP];
    __shared__ float wsB[NWARP];
    __shared__ float gate_sh[2];
    const int wid  = tid >> 5;
    const int lane = tid & 31;
    if (lane == 0) { wsA[wid] = pA; wsB[wid] = pB; }
    __syncthreads();

    // Gate A on warp 0, gate B on warp 1 — parallel serial chains.
    if (tid == 0) {
        float s = bgate[0];
        #pragma unroll
        for (int i = 0; i < NWARP; i++) s += wsA[i];
        const float g = 1.0f / (1.0f + __expf(-s));
        gate_sh[0] = g;
        gate_out[rowA] = g;
    } else if (tid == 32) {
        float s = bgate[0];
        #pragma unroll
        for (int i = 0; i < NWARP; i++) s += wsB[i];
        const float g = 1.0f / (1.0f + __expf(-s));
        gate_sh[1] = g;
        gate_out[rowA + 1] = g;
    }
    __syncthreads();

    const float gA = gate_sh[0];
    const float gB = gate_sh[1];

    float4* __restrict__ mA = (float4*)(mixed + (size_t)rowA * H_DIM);
    float4* __restrict__ mB = mA + F4_ROW;

    float4 r;
    r.x = ovA.x + gA * (dvA.x - ovA.x);
    r.y = ovA.y + gA * (dvA.y - ovA.y);
    r.z = ovA.z + gA * (dvA.z - ovA.z);
    r.w = ovA.w + gA * (dvA.w - ovA.w);
    mA[tid] = r;

    r.x = ovB.x + gB * (dvB.x - ovB.x);
    r.y = ovB.y + gB * (dvB.y - ovB.y);
    r.z = ovB.z + gB * (dvB.z - ovB.z);
    r.w = ovB.w + gB * (dvB.w - ovB.w);
    mB[tid] = r;
}

extern "C" void kernel_launch(void* const* d_in, const int* in_sizes, int n_in,
                              void* d_out, int out_size)
{
    const float* orig  = (const float*)d_in[0];  // original_hidden [B,T,H]
    const float* dag   = (const float*)d_in[1];  // dag_hidden      [B,T,H]
    const float* wgate = (const float*)d_in[2];  // W_gate          [2H,1]
    const float* bgate = (const float*)d_in[3];  // b_gate          [1]

    const int total = in_sizes[0];               // B*T*H
    const int rows  = total / H_DIM;             // B*T (even: 16384)

    float* mixed    = (float*)d_out;             // first B*T*H floats
    float* gate_out = (float*)d_out + total;     // then B*T gate values

    dagmixer_kernel<<<rows / 2, THREADS>>>(orig, dag, wgate, bgate, mixed, gate_out);
}